// round 15
// baseline (speedup 1.0000x reference)
#include <cuda_runtime.h>
#include <cuda_bf16.h>
#include <math.h>

#define Bn 512
#define Kn 512
#define NTH 256
#define GRID 128

struct __align__(16) SmemF {
  __nv_bfloat16 hT_hi[8*136];    // [n][k] transposed h, bf16 hi, padded stride 136
  __nv_bfloat16 hT_lo[8*136];
  float ahst[384][4];
  float h_s[4][128];
  float g_r[4][128];
  float g_z[4][128];
  float g_xn[4][128];
  float g_hn[4][128];
  float lift[4][32];
  float w_ih_s[384*32];
  float b_ih_s[384];
  float b_hh_s[384];
  float w_lift[192];
  float b_lift_s[32];
  float w_head[5][128];
  float feat[4][8];
  float b_head_s[8];
  float u2y_s[12];
  float theta_s[4][8];
};

__device__ __forceinline__ void mma16816(float d[4], const unsigned a[4],
                                         unsigned b0, unsigned b1){
  asm volatile(
    "mma.sync.aligned.m16n8k16.row.col.f32.bf16.bf16.f32 "
    "{%0,%1,%2,%3}, {%4,%5,%6,%7}, {%8,%9}, {%0,%1,%2,%3};"
    : "+f"(d[0]), "+f"(d[1]), "+f"(d[2]), "+f"(d[3])
    : "r"(a[0]), "r"(a[1]), "r"(a[2]), "r"(a[3]), "r"(b0), "r"(b1));
}

__device__ __forceinline__ unsigned pk_hi(float x, float y){
  __nv_bfloat162 v;
  v.x = __float2bfloat16_rn(x);
  v.y = __float2bfloat16_rn(y);
  return *reinterpret_cast<unsigned*>(&v);
}
__device__ __forceinline__ unsigned pk_lo(float x, float y){
  __nv_bfloat16 hx = __float2bfloat16_rn(x);
  __nv_bfloat16 hy = __float2bfloat16_rn(y);
  __nv_bfloat162 v;
  v.x = __float2bfloat16_rn(x - __bfloat162float(hx));
  v.y = __float2bfloat16_rn(y - __bfloat162float(hy));
  return *reinterpret_cast<unsigned*>(&v);
}

__device__ __forceinline__ void ffma2(unsigned long long &acc,
                                      unsigned long long a, unsigned long long b){
  asm("fma.rn.f32x2 %0, %1, %2, %3;" : "=l"(acc) : "l"(a), "l"(b), "l"(acc));
}
__device__ __forceinline__ float f2sum(unsigned long long v){
  float lo, hi;
  asm("mov.b64 {%0,%1}, %2;" : "=f"(lo), "=f"(hi) : "l"(v));
  return lo + hi;
}
__device__ __forceinline__ float sigm(float x){ return 1.0f/(1.0f+__expf(-x)); }
__device__ __forceinline__ float tanh_f(float x){ return 2.0f/(1.0f+__expf(-2.0f*x)) - 1.0f; }

__device__ __forceinline__ void rhs5(const float y[5], const float th[5], float d[5]){
  float r1 = th[0]*y[0]*y[1];
  float r2 = th[1]*y[2];
  float r3 = th[2]*y[2]*y[3];
  float r4 = th[3]*y[4];
  float r5 = th[4]*y[0];
  d[0] = -r1 - r5; d[1] = -r1 + r2; d[2] = r1 - r2 - r3;
  d[3] = -r3 + r4; d[4] = r3 - r4 + r5;
}

__global__ __launch_bounds__(NTH, 1)
void krnn_kernel(const float* __restrict__ y0, const float* __restrict__ u_seq,
    const float* __restrict__ dt_seq, const float* __restrict__ y_seq,
    const float* __restrict__ W_lift, const float* __restrict__ b_lift,
    const float* __restrict__ W_ih, const float* __restrict__ W_hh,
    const float* __restrict__ b_ih, const float* __restrict__ b_hh,
    const float* __restrict__ W_head, const float* __restrict__ b_head,
    const float* __restrict__ u2y, float* __restrict__ out)
{
  extern __shared__ __align__(16) char smraw[];
  SmemF* smf = reinterpret_cast<SmemF*>(smraw);
  const int tid = threadIdx.x;
  const int wr  = tid >> 5;
  const int l   = tid & 31;
  const int b0  = blockIdx.x * 4;

  // ---- load W_hh fragments into registers (bf16 hi/lo), resident forever ----
  // warp wr owns rows [wr*48, wr*48+48): 3 mtiles x 8 ktiles
  unsigned a_hi[3][8][4], a_lo[3][8][4];
  {
    const int gr = l >> 2, tg = l & 3;
    #pragma unroll
    for (int m = 0; m < 3; m++) {
      #pragma unroll
      for (int kt = 0; kt < 8; kt++) {
        int r0 = wr*48 + m*16 + gr;
        int c0 = kt*16 + tg*2;
        const float* p0 = W_hh + r0*128;
        const float* p1 = W_hh + (r0+8)*128;
        float x00 = p0[c0],   x01 = p0[c0+1];
        float x10 = p1[c0],   x11 = p1[c0+1];
        float x02 = p0[c0+8], x03 = p0[c0+9];
        float x12 = p1[c0+8], x13 = p1[c0+9];
        a_hi[m][kt][0] = pk_hi(x00, x01);  a_lo[m][kt][0] = pk_lo(x00, x01);
        a_hi[m][kt][1] = pk_hi(x10, x11);  a_lo[m][kt][1] = pk_lo(x10, x11);
        a_hi[m][kt][2] = pk_hi(x02, x03);  a_lo[m][kt][2] = pk_lo(x02, x03);
        a_hi[m][kt][3] = pk_hi(x12, x13);  a_lo[m][kt][3] = pk_lo(x12, x13);
      }
    }
  }

  // ---- stage small weights / state in smem ----
  for (int i = tid; i < 8*136; i += NTH) { smf->hT_hi[i] = __float2bfloat16_rn(0.f); smf->hT_lo[i] = __float2bfloat16_rn(0.f); }
  for (int i = tid; i < 512; i += NTH) (&smf->h_s[0][0])[i] = 0.0f;
  for (int i = tid; i < 384*32; i += NTH) smf->w_ih_s[i] = W_ih[i];
  for (int i = tid; i < 384; i += NTH) { smf->b_ih_s[i] = b_ih[i]; smf->b_hh_s[i] = b_hh[i]; }
  for (int i = tid; i < 192; i += NTH) smf->w_lift[i] = W_lift[i];
  for (int i = tid; i < 32;  i += NTH) smf->b_lift_s[i] = b_lift[i];
  for (int i = tid; i < 640; i += NTH) (&smf->w_head[0][0])[i] = W_head[i];
  if (tid < 5) smf->b_head_s[tid] = b_head[tid];
  if (tid < 9) smf->u2y_s[tid] = u2y[tid];

  // tail per-sample state (threads 0..3 own sample tid)
  float yst[5] = {0,0,0,0,0};
  float uP0=0.f, uP1=0.f, uP2=0.f, dtP=0.f;
  if (tid < 4) {
    yst[0] = y0[(b0+tid)*3+0];
    yst[2] = y0[(b0+tid)*3+1];
    yst[4] = y0[(b0+tid)*3+2];
  }
  __syncthreads();

  float* out_theta = out + (size_t)Bn*Kn*3;

  for (int k = 0; k <= Kn; ++k) {
    // ======== TAIL (warps 0-4): theta_{k-1}, RK4_{k-1}, feat_k, lift_k ========
    if (tid < 160) {
      if (k > 0) {
        int pair = tid >> 3, j = tid & 7;
        int s = pair / 5, p = pair - 5*s;
        float a = 0.0f;
        #pragma unroll
        for (int m = 0; m < 16; m++) {
          int c = j + 8*m;
          a = fmaf(smf->w_head[p][c], smf->h_s[s][c], a);
        }
        a += __shfl_xor_sync(0xffffffffu, a, 4);
        a += __shfl_xor_sync(0xffffffffu, a, 2);
        a += __shfl_xor_sync(0xffffffffu, a, 1);
        if (j == 0) {
          float th = 0.001f + 1.999f * sigm(a + smf->b_head_s[p]);
          smf->theta_s[s][p] = th;
          out_theta[((size_t)(b0+s)*Kn + (k-1))*5 + p] = th;
        }
      }
      asm volatile("bar.sync 1, 160;" ::: "memory");
      if (tid < 4) {
        int s = tid, b = b0 + s;
        if (k > 0) {
          float y[5], th[5];
          #pragma unroll
          for (int j=0;j<5;j++) y[j] = yst[j];
          y[0] += uP0*smf->u2y_s[0] + uP1*smf->u2y_s[3] + uP2*smf->u2y_s[6];
          y[2] += uP0*smf->u2y_s[1] + uP1*smf->u2y_s[4] + uP2*smf->u2y_s[7];
          y[4] += uP0*smf->u2y_s[2] + uP1*smf->u2y_s[5] + uP2*smf->u2y_s[8];
          #pragma unroll
          for (int p=0;p<5;p++) th[p] = smf->theta_s[s][p];
          float k1[5],k2[5],k3[5],k4[5],ytv[5];
          rhs5(y, th, k1);
          #pragma unroll
          for (int j=0;j<5;j++) ytv[j] = fmaf(0.5f*dtP, k1[j], y[j]);
          rhs5(ytv, th, k2);
          #pragma unroll
          for (int j=0;j<5;j++) ytv[j] = fmaf(0.5f*dtP, k2[j], y[j]);
          rhs5(ytv, th, k3);
          #pragma unroll
          for (int j=0;j<5;j++) ytv[j] = fmaf(dtP, k3[j], y[j]);
          rhs5(ytv, th, k4);
          float c6 = dtP*(1.0f/6.0f);
          #pragma unroll
          for (int j=0;j<5;j++){
            float v = y[j] + c6*(k1[j] + 2.0f*k2[j] + 2.0f*k3[j] + k4[j]);
            yst[j] = fmaxf(v, 0.0f);
          }
          float* oy = out + ((size_t)b*Kn + (k-1))*3;
          oy[0]=yst[0]; oy[1]=yst[2]; oy[2]=yst[4];
        }
        if (k < Kn) {
          const float* up = u_seq + ((size_t)b*Kn + k)*3;
          uP0 = up[0]; uP1 = up[1]; uP2 = up[2];
          dtP = dt_seq[(size_t)b*Kn + k];
          smf->feat[s][0]=uP0; smf->feat[s][1]=uP1; smf->feat[s][2]=uP2;
          bool tf = (k > 0) && ((k % 50) == 0);
          if (tf) {
            const float* yp = y_seq + ((size_t)b*Kn + (k-1))*3;
            smf->feat[s][3]=yp[0]; smf->feat[s][4]=yp[1]; smf->feat[s][5]=yp[2];
          } else {
            smf->feat[s][3]=yst[0]; smf->feat[s][4]=yst[2]; smf->feat[s][5]=yst[4];
          }
        }
      }
      asm volatile("bar.sync 1, 160;" ::: "memory");
      if (tid < 128 && k < Kn) {
        int s = tid >> 5, ll = tid & 31;
        float a = smf->b_lift_s[ll];
        #pragma unroll
        for (int c = 0; c < 6; c++) a = fmaf(smf->w_lift[ll*6+c], smf->feat[s][c], a);
        smf->lift[s][ll] = a * sigm(a);
      }
    }
    if (k == Kn) break;

    // ======== MMA: ah = W_hh . h  (bf16 hi/lo split, A in registers) ========
    {
      float d0[4] = {0,0,0,0}, d1[4] = {0,0,0,0}, d2[4] = {0,0,0,0};
      const int cC = l >> 2, tg = l & 3;
      #pragma unroll
      for (int kt = 0; kt < 8; kt++) {
        int base = cC*136 + kt*16 + tg*2;
        unsigned bh0 = *reinterpret_cast<const unsigned*>(&smf->hT_hi[base]);
        unsigned bh1 = *reinterpret_cast<const unsigned*>(&smf->hT_hi[base + 8]);
        unsigned bl0 = *reinterpret_cast<const unsigned*>(&smf->hT_lo[base]);
        unsigned bl1 = *reinterpret_cast<const unsigned*>(&smf->hT_lo[base + 8]);
        mma16816(d0, a_hi[0][kt], bh0, bh1);
        mma16816(d1, a_hi[1][kt], bh0, bh1);
        mma16816(d2, a_hi[2][kt], bh0, bh1);
        mma16816(d0, a_lo[0][kt], bh0, bh1);
        mma16816(d1, a_lo[1][kt], bh0, bh1);
        mma16816(d2, a_lo[2][kt], bh0, bh1);
        mma16816(d0, a_hi[0][kt], bl0, bl1);
        mma16816(d1, a_hi[1][kt], bl0, bl1);
        mma16816(d2, a_hi[2][kt], bl0, bl1);
      }
      // store D to ahst: lanes with tg<2 hold samples (cols 0-3)
      if (tg < 2) {
        int cc = tg*2, gr = l >> 2;
        int r0 = wr*48 + gr;
        *reinterpret_cast<float2*>(&smf->ahst[r0     ][cc]) = make_float2(d0[0], d0[1]);
        *reinterpret_cast<float2*>(&smf->ahst[r0 +  8][cc]) = make_float2(d0[2], d0[3]);
        *reinterpret_cast<float2*>(&smf->ahst[r0 + 16][cc]) = make_float2(d1[0], d1[1]);
        *reinterpret_cast<float2*>(&smf->ahst[r0 + 24][cc]) = make_float2(d1[2], d1[3]);
        *reinterpret_cast<float2*>(&smf->ahst[r0 + 32][cc]) = make_float2(d2[0], d2[1]);
        *reinterpret_cast<float2*>(&smf->ahst[r0 + 40][cc]) = make_float2(d2[2], d2[3]);
      }
    }
    __syncthreads();   // A: ahst + lift ready

    // ======== phase 2: ax + gates (rows tid and tid+256) ========
    #pragma unroll
    for (int rp = 0; rp < 2; rp++) {
      if (rp == 1 && tid >= 128) break;
      int row = tid + rp*256;
      unsigned long long x0[4], x1[4];
      #pragma unroll
      for (int s=0;s<4;s++){ x0[s]=0ull; x1[s]=0ull; }
      const ulonglong2* wrow = reinterpret_cast<const ulonglong2*>(smf->w_ih_s + row*32);
      #pragma unroll
      for (int l4 = 0; l4 < 8; l4++){
        ulonglong2 wv = wrow[l4];
        #pragma unroll
        for (int s=0;s<4;s++){
          ulonglong2 lv = *reinterpret_cast<const ulonglong2*>(&smf->lift[s][l4*4]);
          ffma2(x0[s], wv.x, lv.x);
          ffma2(x1[s], wv.y, lv.y);
        }
      }
      float bx = smf->b_ih_s[row], bh = smf->b_hh_s[row];
      float4 av = *reinterpret_cast<const float4*>(&smf->ahst[row][0]);
      float ahf[4] = {av.x+bh, av.y+bh, av.z+bh, av.w+bh};
      float axf[4];
      #pragma unroll
      for (int s=0;s<4;s++) axf[s] = f2sum(x0[s]) + f2sum(x1[s]) + bx;
      int third = row >> 7, rr = row & 127;
      if (third == 0) {
        #pragma unroll
        for (int s=0;s<4;s++) smf->g_r[s][rr] = axf[s] + ahf[s];
      } else if (third == 1) {
        #pragma unroll
        for (int s=0;s<4;s++) smf->g_z[s][rr] = axf[s] + ahf[s];
      } else {
        #pragma unroll
        for (int s=0;s<4;s++){ smf->g_xn[s][rr] = axf[s]; smf->g_hn[s][rr] = ahf[s]; }
      }
    }
    __syncthreads();   // B: gates ready

    // ======== GRU: update h_s fp32 + hT bf16 hi/lo ========
    #pragma unroll
    for (int e = tid; e < 512; e += NTH) {
      int s = e >> 7, t = e & 127;
      float rgt = sigm(smf->g_r[s][t]);
      float zg  = sigm(smf->g_z[s][t]);
      float nn  = tanh_f(fmaf(rgt, smf->g_hn[s][t], smf->g_xn[s][t]));
      float hn  = (1.0f - zg)*nn + zg*smf->h_s[s][t];
      smf->h_s[s][t] = hn;
      __nv_bfloat16 hi = __float2bfloat16_rn(hn);
      __nv_bfloat16 lo = __float2bfloat16_rn(hn - __bfloat162float(hi));
      smf->hT_hi[s*136 + t] = hi;
      smf->hT_lo[s*136 + t] = lo;
    }
    __syncthreads();   // C: h_{k+1} published
  }
}

extern "C" void kernel_launch(void* const* d_in, const int* in_sizes, int n_in,
                              void* d_out, int out_size) {
  const float* y0     = (const float*)d_in[0];
  const float* u_seq  = (const float*)d_in[1];
  const float* dt_seq = (const float*)d_in[2];
  const float* y_seq  = (const float*)d_in[3];
  const float* W_lift = (const float*)d_in[4];
  const float* b_lift = (const float*)d_in[5];
  const float* W_ih   = (const float*)d_in[6];
  const float* W_hh   = (const float*)d_in[7];
  const float* b_ih   = (const float*)d_in[8];
  const float* b_hh   = (const float*)d_in[9];
  const float* W_head = (const float*)d_in[10];
  const float* b_head = (const float*)d_in[11];
  const float* u2y    = (const float*)d_in[12];
  float* out = (float*)d_out;

  cudaFuncSetAttribute(krnn_kernel, cudaFuncAttributeMaxDynamicSharedMemorySize,
                       (int)sizeof(SmemF));
  krnn_kernel<<<GRID, NTH, sizeof(SmemF)>>>(y0, u_seq, dt_seq, y_seq, W_lift, b_lift,
                                            W_ih, W_hh, b_ih, b_hh, W_head, b_head,
                                            u2y, out);
}